// round 16
// baseline (speedup 1.0000x reference)
#include <cuda_runtime.h>
#include <cstdint>

#define SEQ 2048
#define EMB 2048
#define NB 2
#define NH 16
#define HD 128
#define MTOT (NB*SEQ)
#define FST 132   // flash smem row stride (128 + 4 pad)

// Scratch (allocation-free rule: __device__ globals)
__device__ float g_q[(size_t)MTOT * EMB];     // rope-applied, tf32-rounded
__device__ float g_k[(size_t)MTOT * EMB];     // rope-applied, tf32-rounded
__device__ float g_v[(size_t)MTOT * EMB];     // V^T per head: [(b*NH+h)][d][s], tf32-rounded
__device__ float g_o[(size_t)MTOT * EMB];     // flash writes tf32-rounded O
__device__ float g_x[(size_t)MTOT * EMB];     // tf32-rounded X
__device__ float g_wq[(size_t)EMB * EMB];     // tf32-rounded weights
__device__ float g_wk[(size_t)EMB * EMB];
__device__ float g_wv[(size_t)EMB * EMB];
__device__ float g_wo[(size_t)EMB * EMB];
__device__ float g_cos[SEQ * (HD/2)];
__device__ float g_sin[SEQ * (HD/2)];

__device__ __forceinline__ uint32_t f2tf(float x){
  uint32_t y; asm("cvt.rna.tf32.f32 %0, %1;" : "=r"(y) : "f"(x)); return y;
}
__device__ __forceinline__ float f2tff(float x){ return __uint_as_float(f2tf(x)); }

__device__ __forceinline__ uint32_t smem_u32(const void* p){
  uint32_t a;
  asm("{ .reg .u64 t; cvta.to.shared.u64 t, %1; cvt.u32.u64 %0, t; }" : "=r"(a) : "l"(p));
  return a;
}

__device__ __forceinline__ void cp16(uint32_t dst, const void* src){
  asm volatile("cp.async.cg.shared.global [%0], [%1], 16;" :: "r"(dst), "l"(src));
}
#define CP_COMMIT() asm volatile("cp.async.commit_group;" ::: "memory")
#define CP_WAIT1()  asm volatile("cp.async.wait_group 1;" ::: "memory")
#define CP_WAIT0()  asm volatile("cp.async.wait_group 0;" ::: "memory")

__device__ __forceinline__ void mma8(float* d, const uint32_t* a, const uint32_t* b){
  asm volatile("mma.sync.aligned.m16n8k8.row.col.f32.tf32.tf32.f32 "
    "{%0,%1,%2,%3},{%4,%5,%6,%7},{%8,%9},{%0,%1,%2,%3};\n"
    : "+f"(d[0]), "+f"(d[1]), "+f"(d[2]), "+f"(d[3])
    : "r"(a[0]), "r"(a[1]), "r"(a[2]), "r"(a[3]), "r"(b[0]), "r"(b[1]));
}

// ldmatrix x4: four 8x(4xtf32) chunks; thread l -> (row l/4, tf32-col l%4)
__device__ __forceinline__ void ldsm4(uint32_t* r, uint32_t addr){
  asm volatile("ldmatrix.sync.aligned.m8n8.x4.shared.b16 {%0,%1,%2,%3}, [%4];"
    : "=r"(r[0]), "=r"(r[1]), "=r"(r[2]), "=r"(r[3]) : "r"(addr));
}

// ---------------------------------------------------------------------------
// TF32 pre-rounding: ONE launch covers X (2M float4) + 4 weights (1M each)
// ---------------------------------------------------------------------------
__global__ void round_all_kernel(const float* __restrict__ x,
                                 const float* __restrict__ wq, const float* __restrict__ wk,
                                 const float* __restrict__ wv, const float* __restrict__ wo,
                                 float* __restrict__ px,
                                 float* __restrict__ pwq, float* __restrict__ pwk,
                                 float* __restrict__ pwv, float* __restrict__ pwo){
  int i = blockIdx.x*blockDim.x + threadIdx.x;   // 0 .. 6M-1 float4
  const float* src; float* dst; int off;
  if (i < (1<<21)){ src = x; dst = px; off = i; }
  else {
    int r = i - (1<<21);
    int which = r >> 20;
    off = r & ((1<<20)-1);
    src = (which==0)? wq : (which==1)? wk : (which==2)? wv : wo;
    dst = (which==0)? pwq : (which==1)? pwk : (which==2)? pwv : pwo;
  }
  float4 v = ((const float4*)src)[off];
  v.x=f2tff(v.x); v.y=f2tff(v.y); v.z=f2tff(v.z); v.w=f2tff(v.w);
  ((float4*)dst)[off] = v;
}

// ---------------------------------------------------------------------------
// RoPE tables
// ---------------------------------------------------------------------------
__global__ void rope_tables_kernel(){
  int idx = blockIdx.x*blockDim.x + threadIdx.x;
  if (idx >= SEQ*(HD/2)) return;
  int s = idx >> 6;
  int j = idx & 63;
  double inv = pow(10000.0, -(double)j/64.0);
  float ang = (float)s * (float)inv;
  g_cos[idx] = (float)cos((double)ang);
  g_sin[idx] = (float)sin((double)ang);
}

// ---------------------------------------------------------------------------
// GEMM: C[M,N] = A[M,K] @ W[N,K]^T + bias[N]
// BM=BN=128, BK=32, 256 threads, TF32 m16n8k8, ldmatrix frags.
// 3-stage cp.async pipeline, ONE __syncthreads per k-tile.
// modeArg=-1: QKV fused (mode = blockIdx.z): 0=Q+RoPE, 1=K+RoPE, 2=V transposed.
// modeArg=3: A=g_o, C=Out (fp32).
// ---------------------------------------------------------------------------
#define GST 36
#define TILE_F (128*GST)          // floats per A (or B) stage half
#define STAGE_B (2*TILE_F*4)      // bytes per stage (A+B) = 36864
#define G_SMEM_BYTES (3*STAGE_B)  // 110592
#define EXST 130
#define EXST_V 132

__global__ __launch_bounds__(256,2) void gemm_bias_kernel(
    const float* __restrict__ biasq, const float* __restrict__ biask,
    const float* __restrict__ biasv, float* __restrict__ Outp, int modeArg)
{
  extern __shared__ float smg[];   // 3 stages of [A(128x36) | B(128x36)]

  const int mode = (modeArg < 0) ? (int)blockIdx.z : modeArg;
  const float* bias = (mode==0) ? biasq : (mode==1) ? biask : biasv;
  const float* A = (mode == 3) ? g_o : g_x;
  const float* W = (mode==0) ? g_wq : (mode==1) ? g_wk : (mode==2) ? g_wv : g_wo;

  const int tid = threadIdx.x;
  const int bn = blockIdx.x, bm = blockIdx.y;
  const int lane = tid & 31, w = tid >> 5;
  const int wm = (w >> 1) << 5;
  const int wn = (w & 1) << 6;
  const int g = lane >> 2, t4 = lane & 3;
  const int q8 = lane >> 3, r8 = lane & 7;

  const int prow = tid >> 3;
  const int pf4  = (tid & 7) << 2;
  const float* Ag = A + (size_t)(bm*128 + prow) * EMB + pf4;
  const float* Wg = W + (size_t)(bn*128 + prow) * EMB + pf4;

  const uint32_t base = smem_u32(smg);
  const uint32_t sA = base + (prow*GST + pf4)*4;
  const uint32_t sB = base + TILE_F*4 + (prow*GST + pf4)*4;

  uint32_t offA[2], offB[4];
  #pragma unroll
  for (int mt=0; mt<2; mt++)
    offA[mt] = (uint32_t)(((wm + mt*16 + ((q8&1)<<3) + r8)*GST + ((q8>>1)<<2))*4);
  #pragma unroll
  for (int j=0; j<4; j++)
    offB[j] = (uint32_t)(((wn + j*16 + ((q8>>1)<<3) + r8)*GST + ((q8&1)<<2))*4);

  float acc[2][8][4];
  #pragma unroll
  for (int mt=0;mt<2;mt++)
    #pragma unroll
    for (int nt=0;nt<8;nt++)
      #pragma unroll
      for (int e=0;e<4;e++) acc[mt][nt][e] = 0.f;

  // prologue: stages 0,1
  #pragma unroll
  for (int s = 0; s < 2; s++){
    #pragma unroll
    for (int i = 0; i < 4; i++){
      cp16(sA + s*STAGE_B + i*32*GST*4, Ag + s*32 + (size_t)i*32*EMB);
      cp16(sB + s*STAGE_B + i*32*GST*4, Wg + s*32 + (size_t)i*32*EMB);
    }
    CP_COMMIT();
  }

  for (int kt = 0; kt < 64; kt++){
    CP_WAIT1();            // stage kt resident (kt+1 may be in flight)
    __syncthreads();       // single barrier: fences last iter's reads too
    if (kt < 62){
      const int ns = (kt+2) % 3;
      #pragma unroll
      for (int i = 0; i < 4; i++){
        cp16(sA + ns*STAGE_B + i*32*GST*4, Ag + (kt+2)*32 + (size_t)i*32*EMB);
        cp16(sB + ns*STAGE_B + i*32*GST*4, Wg + (kt+2)*32 + (size_t)i*32*EMB);
      }
    }
    CP_COMMIT();           // unconditional: keeps group counting uniform

    const uint32_t soff = (uint32_t)((kt % 3) * STAGE_B);
    const uint32_t abase = base + soff;
    const uint32_t bbase = base + TILE_F*4 + soff;
    #pragma unroll
    for (int ks = 0; ks < 4; ks++){
      uint32_t af[2][4], bf[4][4];
      ldsm4(af[0], abase + offA[0] + ks*32);
      ldsm4(af[1], abase + offA[1] + ks*32);
      #pragma unroll
      for (int j=0;j<4;j++) ldsm4(bf[j], bbase + offB[j] + ks*32);
      #pragma unroll
      for (int mt=0; mt<2; mt++)
        #pragma unroll
        for (int j=0; j<4; j++){
          mma8(acc[mt][2*j],   af[mt], &bf[j][0]);
          mma8(acc[mt][2*j+1], af[mt], &bf[j][2]);
        }
    }
  }
  __syncthreads();         // all warps done with smem before epilogue reuse

  if (mode <= 1){
    float* C = (mode==0) ? g_q : g_k;
    float* ex = smg;
    #pragma unroll
    for (int mt=0; mt<2; mt++){
      #pragma unroll
      for (int nt=0; nt<8; nt++){
        int colL = wn + nt*8 + 2*t4;
        float b0 = bias[bn*128 + colL], b1 = bias[bn*128 + colL + 1];
        int r0 = wm + mt*16 + g;
        ex[r0*EXST + colL]     = acc[mt][nt][0] + b0;
        ex[r0*EXST + colL + 1] = acc[mt][nt][1] + b1;
        ex[(r0+8)*EXST + colL]     = acc[mt][nt][2] + b0;
        ex[(r0+8)*EXST + colL + 1] = acc[mt][nt][3] + b1;
      }
    }
    __syncthreads();
    #pragma unroll
    for (int mt=0; mt<2; mt++){
      #pragma unroll
      for (int hh=0; hh<2; hh++){
        int rowL = wm + mt*16 + g + hh*8;
        int m = bm*128 + rowL;
        int s = m & (SEQ-1);
        float* Crow = C + (size_t)m * EMB + bn*128;
        #pragma unroll
        for (int nt=0; nt<8; nt++){
          int j = ((wn >> 1) + nt*4 + t4) & 63;
          float c = g_cos[s*64 + j], sn = g_sin[s*64 + j];
          float v1 = ex[rowL*EXST + j];
          float v2 = ex[rowL*EXST + j + 64];
          Crow[j]      = f2tff(v1*c - v2*sn);
          Crow[j + 64] = f2tff(v1*sn + v2*c);
        }
      }
    }
  } else if (mode == 2){
    float* ex = smg;
    #pragma unroll
    for (int mt=0; mt<2; mt++){
      #pragma unroll
      for (int nt=0; nt<8; nt++){
        int colL = wn + nt*8 + 2*t4;
        float b0 = bias[bn*128 + colL], b1 = bias[bn*128 + colL + 1];
        int r0 = wm + mt*16 + g;
        ex[colL*EXST_V + r0]       = f2tff(acc[mt][nt][0] + b0);
        ex[(colL+1)*EXST_V + r0]   = f2tff(acc[mt][nt][1] + b1);
        ex[colL*EXST_V + r0+8]     = f2tff(acc[mt][nt][2] + b0);
        ex[(colL+1)*EXST_V + r0+8] = f2tff(acc[mt][nt][3] + b1);
      }
    }
    __syncthreads();
    const int d  = tid >> 1;
    const int sh = (tid & 1) << 6;
    const int bb = bm >> 4;
    const int s_base = (bm & 15) * 128;
    float* Vt = g_v + (((size_t)(bb*NH + bn))*HD + d)*SEQ + s_base + sh;
    const float* exr = ex + d*EXST_V + sh;
    #pragma unroll
    for (int i = 0; i < 16; i++)
      *(float4*)&Vt[i*4] = *(const float4*)&exr[i*4];
  } else {
    #pragma unroll
    for (int mt=0; mt<2; mt++){
      int row = bm*128 + wm + mt*16 + g;
      #pragma unroll
      for (int nt=0; nt<8; nt++){
        int col = bn*128 + wn + nt*8 + 2*t4;
        float b0 = biasq[col], b1 = biasq[col+1];
        float2 v0 = make_float2(acc[mt][nt][0]+b0, acc[mt][nt][1]+b1);
        float2 v1 = make_float2(acc[mt][nt][2]+b0, acc[mt][nt][3]+b1);
        *(float2*)&Outp[(size_t)row*EMB + col] = v0;
        *(float2*)&Outp[(size_t)(row+8)*EMB + col] = v1;
      }
    }
  }
}

// ---------------------------------------------------------------------------
// Flash attention, causal (exact R12 proven form): 256 thr, 4x2 warps,
// ldmatrix Q/K/P/V^T, split K/V cp.async groups, qt-descending grid.
// ---------------------------------------------------------------------------
#define FLASH_SMEM_FLOATS (3*128*FST + 256 + 256 + 128)

__global__ __launch_bounds__(256,1) void flash_kernel(const unsigned char* __restrict__ amask){
  extern __shared__ float sm[];
  float* Qs   = sm;
  float* Ks   = sm + 128*FST;
  float* Vs   = sm + 2*128*FST;       // V^T tile: [d=0..127][s=0..127]
  float* redm = sm + 3*128*FST;
  float* reds = redm + 256;
  float* km   = reds + 256;

  const int tid = threadIdx.x;
  const int bh = blockIdx.x;
  const int qt = (int)(gridDim.y - 1) - (int)blockIdx.y;  // long CTAs first
  const int b = bh >> 4, h = bh & 15;
  const int lane = tid & 31, w = tid >> 5;
  const int wm = (w >> 1) << 5;
  const int wnn = (w & 1);
  const int wn = wnn << 6;
  const int g = lane >> 2, t4 = lane & 3;
  const int q8 = lane >> 3, r8 = lane & 7;

  const size_t headoff = (size_t)h * HD;
  const int lr = tid >> 5;
  const int lc = (tid & 31) << 2;

  const float* Qg = g_q + ((size_t)(b*SEQ + qt*128) + lr) * EMB + headoff + lc;
  const uint32_t qbase = smem_u32(Qs), kbase = smem_u32(Ks), vbase = smem_u32(Vs);
  const uint32_t sQ = qbase + (lr*FST + lc)*4;
  const uint32_t sK = kbase + (lr*FST + lc)*4;
  const uint32_t sV = vbase + (lr*FST + lc)*4;

  uint32_t offQA[2], offKB[4];
  #pragma unroll
  for (int mt=0; mt<2; mt++)
    offQA[mt] = (uint32_t)(((wm + mt*16 + ((q8&1)<<3) + r8)*FST + ((q8>>1)<<2))*4);
  #pragma unroll
  for (int j=0; j<4; j++)
    offKB[j] = (uint32_t)(((wn + j*16 + ((q8>>1)<<3) + r8)*FST + ((q8&1)<<2))*4);

  #pragma unroll
  for (int i = 0; i < 16; i++)
    cp16(sQ + i*8*FST*4, Qg + (size_t)i*8*EMB);
  CP_COMMIT();

  float o_acc[2][8][4];
  #pragma unroll
  for (int mt=0;mt<2;mt++)
    #pragma unroll
    for (int nt=0;nt<8;nt++)
      #pragma unroll
      for (int e=0;e<4;e++) o_acc[mt][nt][e] = 0.f;
  float m_prev[4], l_run[4];
  #pragma unroll
  for (int ri=0;ri<4;ri++){ m_prev[ri] = -1e30f; l_run[ri] = 0.f; }

  const float scale = 0.088388347648318447f;

  for (int kt = 0; kt <= qt; kt++){
    __syncthreads();   // prior PV reads of Ks/Vs done before refill
    const float* Kg = g_k + ((size_t)(b*SEQ + kt*128) + lr) * EMB + headoff + lc;
    const float* Vg = g_v + ((size_t)bh*HD + lr)*SEQ + kt*128 + lc;
    #pragma unroll
    for (int i = 0; i < 16; i++)
      cp16(sK + i*8*FST*4, Kg + (size_t)i*8*EMB);
    CP_COMMIT();       // group A: K
    #pragma unroll
    for (int i = 0; i < 16; i++)
      cp16(sV + i*8*FST*4, Vg + (size_t)i*8*SEQ);
    CP_COMMIT();       // group B: V
    if (tid < 128) km[tid] = amask[b*SEQ + kt*128 + tid] ? -1e30f : 0.f;
    CP_WAIT1();        // K (and Q on first iter) resident; V may be in flight
    __syncthreads();

    // ---- S = Q K^T ----
    float s_acc[2][8][4];
    #pragma unroll
    for (int mt=0;mt<2;mt++)
      #pragma unroll
      for (int nt=0;nt<8;nt++)
        #pragma unroll
        for (int e=0;e<4;e++) s_acc[mt][nt][e] = 0.f;

    #pragma unroll
    for (int ks=0; ks<16; ks++){
      uint32_t af[2][4], bf[4][4];
      ldsm4(af[0], qbase + offQA[0] + ks*32);
      ldsm4(af[1], qbase + offQA[1] + ks*32);
      #pragma unroll
      for (int j=0;j<4;j++) ldsm4(bf[j], kbase + offKB[j] + ks*32);
      #pragma unroll
      for (int mt=0;mt<2;mt++)
        #pragma unroll
        for (int j=0;j<4;j++){
          mma8(s_acc[mt][2*j],   af[mt], &bf[j][0]);
          mma8(s_acc[mt][2*j+1], af[mt], &bf[j][2]);
        }
    }

    const bool diag = (kt == qt);
    #pragma unroll
    for (int mt=0;mt<2;mt++)
      #pragma unroll
      for (int nt=0;nt<8;nt++)
        #pragma unroll
        for (int e=0;e<4;e++){
          int colL = wn + nt*8 + 2*t4 + (e & 1);
          int rowL = wm + mt*16 + g + ((e >> 1) << 3);
          float v = s_acc[mt][nt][e]*scale + km[colL];
          if (diag && colL > rowL) v = -1e30f;
          s_acc[mt][nt][e] = v;
        }

    #pragma unroll
    for (int ri=0;ri<4;ri++){
      int mt = ri>>1, hh = ri&1;
      float mx = -1e30f;
      #pragma unroll
      for (int nt=0;nt<8;nt++)
        mx = fmaxf(mx, fmaxf(s_acc[mt][nt][hh*2], s_acc[mt][nt][hh*2+1]));
      mx = fmaxf(mx, __shfl_xor_sync(0xffffffffu, mx, 1));
      mx = fmaxf(mx, __shfl_xor_sync(0xffffffffu, mx, 2));
      if (t4 == 0) redm[wnn*128 + wm + mt*16 + g + hh*8] = mx;
    }
    __syncthreads();

    float m_new[4], alpha[4], rsum[4];
    #pragma unroll
    for (int ri=0;ri<4;ri++){
      int rl = wm + (ri>>1)*16 + g + (ri&1)*8;
      float mtile = fmaxf(redm[rl], redm[128+rl]);
      m_new[ri] = fmaxf(m_prev[ri], mtile);
      alpha[ri] = __expf(m_prev[ri] - m_new[ri]);
      rsum[ri] = 0.f;
    }

    #pragma unroll
    for (int mt=0;mt<2;mt++)
      #pragma unroll
      for (int nt=0;nt<8;nt++)
        #pragma unroll
        for (int hh=0;hh<2;hh++){
          int ri = mt*2 + hh;
          float p0 = __expf(s_acc[mt][nt][hh*2]   - m_new[ri]);
          float p1 = __expf(s_acc[mt][nt][hh*2+1] - m_new[ri]);
          rsum[ri] += p0 + p1;
          int rowL = wm + mt*16 + g + hh*8;
          int colL = wn + nt*8 + 2*t4;
          float2 pv; pv.x = f2tff(p0); pv.y = f2tff(p1);
          *(float2*)&Ks[rowL*FST + colL] = pv;
          o_acc[mt][nt][hh*2]   *= alpha[ri];
          o_acc[mt][nt][hh*2+1] *= alpha[ri];
        }

    #pragma unroll
    for (int ri=0;ri<4;ri++){
      float s0 = rsum[ri];
      s0 += __shfl_xor_sync(0xffffffffu, s0, 1);
      s0 += __shfl_xor_sync(0xffffffffu, s0, 2);
      if (t4 == 0) reds[wnn*128 + wm + (ri>>1)*16 + g + (ri&1)*8] = s0;
    }
    CP_WAIT0();        // V resident (hidden behind S + softmax)
    __syncthreads();   // P + sums + V all visible
    #pragma unroll
    for (int ri=0;ri<4;ri++){
      int rl = wm + (ri>>1)*16 + g + (ri&1)*8;
      l_run[ri] = l_run[ri]*alpha[ri] + reds[rl] + reds[128+rl];
      m_prev[ri] = m_new[ri];
    }

    // ---- O += P @ V ----
    #pragma unroll
    for (int ks=0; ks<16; ks++){
      uint32_t af[2][4], bf[4][4];
      ldsm4(af[0], kbase + offQA[0] + ks*32);
      ldsm4(af[1], kbase + offQA[1] + ks*32);
      #pragma unroll
      for (int j=0;j<4;j++) ldsm4(bf[j], vbase + offKB[j] + ks*32);
      #pragma unroll
      for (int mt=0;mt<2;mt++)
        #pragma unroll
        for (int j=0;j<4;j++){
          mma8(o_acc[mt][2*j],   af[mt], &bf[j][0]);
          mma8(o_acc[mt][2*j+1], af[mt], &bf[j][2]);
        }
    }
  }

  float* Og = g_o + ((size_t)(b*SEQ + qt*128)) * EMB + headoff;
  #pragma unroll
  for (int mt=0;mt<2;mt++)
    #pragma unroll
    for (int hh=0;hh<2;hh++){
      int ri = mt*2 + hh;
      float inv = 1.0f / l_run[ri];
      int rowL = wm + mt*16 + g + hh*8;
      #pragma unroll
      for (int nt=0;nt<8;nt++){
        int colL = wn + nt*8 + 2*t4;
        float2 ov;
        ov.x = f2tff(o_acc[mt][nt][hh*2]   * inv);
        ov.y = f2tff(o_acc[mt][nt][hh*2+1] * inv);
        *(float2*)&Og[(size_t)rowL*EMB + colL] = ov;
      }
    }
}

// ---------------------------------------------------------------------------
extern "C" void kernel_launch(void* const* d_in, const int* in_sizes, int n_in,
                              void* d_out, int out_size){
  (void)in_sizes; (void)n_in; (void)out_size;
  const float* x  = (const float*)d_in[0];
  const float* wq = (const float*)d_in[1];
  const float* bq = (const float*)d_in[2];
  const float* wk = (const float*)d_in[3];
  const float* bk = (const float*)d_in[4];
  const float* wv = (const float*)d_in[5];
  const float* bv = (const float*)d_in[6];
  const float* wo = (const float*)d_in[7];
  const float* bo = (const float*)d_in[8];
  const unsigned char* amask = (const unsigned char*)d_in[10];
  float* out = (float*)d_out;

  cudaFuncSetAttribute(flash_kernel, cudaFuncAttributeMaxDynamicSharedMemorySize,
                       FLASH_SMEM_FLOATS * (int)sizeof(float));
  cudaFuncSetAttribute(gemm_bias_kernel, cudaFuncAttributeMaxDynamicSharedMemorySize,
                       G_SMEM_BYTES);

  float *p_x, *p_wq, *p_wk, *p_wv, *p_wo;
  cudaGetSymbolAddress((void**)&p_x,  g_x);
  cudaGetSymbolAddress((void**)&p_wq, g_wq);
  cudaGetSymbolAddress((void**)&p_wk, g_wk);
  cudaGetSymbolAddress((void**)&p_wv, g_wv);
  cudaGetSymbolAddress((void**)&p_wo, g_wo);

  rope_tables_kernel<<<(SEQ*64 + 255)/256, 256>>>();

  const int nAll4 = (1<<21) + 4*(1<<20);
  round_all_kernel<<<(nAll4+255)/256, 256>>>(x, wq, wk, wv, wo,
                                             p_x, p_wq, p_wk, p_wv, p_wo);

  gemm_bias_kernel<<<dim3(EMB/128, MTOT/128, 3), 256, G_SMEM_BYTES>>>(bq, bk, bv, nullptr, -1);

  flash_kernel<<<dim3(NB*NH, SEQ/128), 256, FLASH_SMEM_FLOATS*(int)sizeof(float)>>>(amask);

  gemm_bias_kernel<<<dim3(EMB/128, MTOT/128, 1), 256, G_SMEM_BYTES>>>(bo, bo, bo, out, 3);
}

// round 17
// speedup vs baseline: 1.0206x; 1.0206x over previous
#include <cuda_runtime.h>
#include <cstdint>

#define SEQ 2048
#define EMB 2048
#define NB 2
#define NH 16
#define HD 128
#define MTOT (NB*SEQ)
#define FST 132   // flash smem row stride (128 + 4 pad)

// Scratch (allocation-free rule: __device__ globals)
__device__ float g_q[(size_t)MTOT * EMB];     // rope-applied, tf32-rounded
__device__ float g_k[(size_t)MTOT * EMB];     // rope-applied, tf32-rounded
__device__ float g_v[(size_t)MTOT * EMB];     // V^T per head: [(b*NH+h)][d][s], tf32-rounded
__device__ float g_o[(size_t)MTOT * EMB];     // flash writes tf32-rounded O
__device__ float g_x[(size_t)MTOT * EMB];     // tf32-rounded X
__device__ float g_wq[(size_t)EMB * EMB];     // tf32-rounded weights
__device__ float g_wk[(size_t)EMB * EMB];
__device__ float g_wv[(size_t)EMB * EMB];
__device__ float g_wo[(size_t)EMB * EMB];
__device__ float g_cos[SEQ * (HD/2)];
__device__ float g_sin[SEQ * (HD/2)];

__device__ __forceinline__ uint32_t f2tf(float x){
  uint32_t y; asm("cvt.rna.tf32.f32 %0, %1;" : "=r"(y) : "f"(x)); return y;
}
__device__ __forceinline__ float f2tff(float x){ return __uint_as_float(f2tf(x)); }

__device__ __forceinline__ uint32_t smem_u32(const void* p){
  uint32_t a;
  asm("{ .reg .u64 t; cvta.to.shared.u64 t, %1; cvt.u32.u64 %0, t; }" : "=r"(a) : "l"(p));
  return a;
}

__device__ __forceinline__ void cp16(uint32_t dst, const void* src){
  asm volatile("cp.async.cg.shared.global [%0], [%1], 16;" :: "r"(dst), "l"(src));
}
#define CP_COMMIT() asm volatile("cp.async.commit_group;" ::: "memory")
#define CP_WAIT1()  asm volatile("cp.async.wait_group 1;" ::: "memory")
#define CP_WAIT0()  asm volatile("cp.async.wait_group 0;" ::: "memory")

__device__ __forceinline__ void mma8(float* d, const uint32_t* a, const uint32_t* b){
  asm volatile("mma.sync.aligned.m16n8k8.row.col.f32.tf32.tf32.f32 "
    "{%0,%1,%2,%3},{%4,%5,%6,%7},{%8,%9},{%0,%1,%2,%3};\n"
    : "+f"(d[0]), "+f"(d[1]), "+f"(d[2]), "+f"(d[3])
    : "r"(a[0]), "r"(a[1]), "r"(a[2]), "r"(a[3]), "r"(b[0]), "r"(b[1]));
}

// ldmatrix x4: four 8x(4xtf32) chunks; thread l -> (row l/4, tf32-col l%4)
__device__ __forceinline__ void ldsm4(uint32_t* r, uint32_t addr){
  asm volatile("ldmatrix.sync.aligned.m8n8.x4.shared.b16 {%0,%1,%2,%3}, [%4];"
    : "=r"(r[0]), "=r"(r[1]), "=r"(r[2]), "=r"(r[3]) : "r"(addr));
}

// ---------------------------------------------------------------------------
// TF32 pre-rounding: ONE launch covers X (2M float4) + 4 weights (1M each)
// ---------------------------------------------------------------------------
__global__ void round_all_kernel(const float* __restrict__ x,
                                 const float* __restrict__ wq, const float* __restrict__ wk,
                                 const float* __restrict__ wv, const float* __restrict__ wo,
                                 float* __restrict__ px,
                                 float* __restrict__ pwq, float* __restrict__ pwk,
                                 float* __restrict__ pwv, float* __restrict__ pwo){
  int i = blockIdx.x*blockDim.x + threadIdx.x;   // 0 .. 6M-1 float4
  const float* src; float* dst; int off;
  if (i < (1<<21)){ src = x; dst = px; off = i; }
  else {
    int r = i - (1<<21);
    int which = r >> 20;
    off = r & ((1<<20)-1);
    src = (which==0)? wq : (which==1)? wk : (which==2)? wv : wo;
    dst = (which==0)? pwq : (which==1)? pwk : (which==2)? pwv : pwo;
  }
  float4 v = ((const float4*)src)[off];
  v.x=f2tff(v.x); v.y=f2tff(v.y); v.z=f2tff(v.z); v.w=f2tff(v.w);
  ((float4*)dst)[off] = v;
}

// ---------------------------------------------------------------------------
// RoPE tables
// ---------------------------------------------------------------------------
__global__ void rope_tables_kernel(){
  int idx = blockIdx.x*blockDim.x + threadIdx.x;
  if (idx >= SEQ*(HD/2)) return;
  int s = idx >> 6;
  int j = idx & 63;
  double inv = pow(10000.0, -(double)j/64.0);
  float ang = (float)s * (float)inv;
  g_cos[idx] = (float)cos((double)ang);
  g_sin[idx] = (float)sin((double)ang);
}

// ---------------------------------------------------------------------------
// GEMM (champion R12 config): C[M,N] = A[M,K] @ W[N,K]^T + bias[N]
// BM=BN=128, BK=32, 256 threads, TF32 m16n8k8, cp.async x2 static smem,
// ldmatrix frags. modeArg=-1: QKV fused via blockIdx.z (0=Q+RoPE, 1=K+RoPE,
// 2=V transposed). modeArg=3: A=g_o, C=Out (fp32).
// ---------------------------------------------------------------------------
#define GST 36
#define TILE_F (128*GST)
#define EXST 130
#define EXST_V 132

__global__ __launch_bounds__(256,2) void gemm_bias_kernel(
    const float* __restrict__ biasq, const float* __restrict__ biask,
    const float* __restrict__ biasv, float* __restrict__ Outp, int modeArg)
{
  __shared__ float smg[4*TILE_F];   // As[2 stages] + Bs[2 stages], also epilogue ex
  float* As = smg;
  float* Bs = smg + 2*TILE_F;

  const int mode = (modeArg < 0) ? (int)blockIdx.z : modeArg;
  const float* bias = (mode==0) ? biasq : (mode==1) ? biask : biasv;
  const float* A = (mode == 3) ? g_o : g_x;
  const float* W = (mode==0) ? g_wq : (mode==1) ? g_wk : (mode==2) ? g_wv : g_wo;

  const int tid = threadIdx.x;
  const int bn = blockIdx.x, bm = blockIdx.y;
  const int lane = tid & 31, w = tid >> 5;
  const int wm = (w >> 1) << 5;
  const int wn = (w & 1) << 6;
  const int g = lane >> 2, t4 = lane & 3;
  const int q8 = lane >> 3, r8 = lane & 7;

  const int prow = tid >> 3;
  const int pf4  = (tid & 7) << 2;
  const float* Ag = A + (size_t)(bm*128 + prow) * EMB + pf4;
  const float* Wg = W + (size_t)(bn*128 + prow) * EMB + pf4;
  const uint32_t sAs = smem_u32(As) + (prow*GST + pf4)*4;
  const uint32_t sBs = smem_u32(Bs) + (prow*GST + pf4)*4;

  uint32_t offA[2], offB[4];
  #pragma unroll
  for (int mt=0; mt<2; mt++)
    offA[mt] = (uint32_t)(((wm + mt*16 + ((q8&1)<<3) + r8)*GST + ((q8>>1)<<2))*4);
  #pragma unroll
  for (int j=0; j<4; j++)
    offB[j] = (uint32_t)(((wn + j*16 + ((q8>>1)<<3) + r8)*GST + ((q8&1)<<2))*4);
  const uint32_t abase0 = smem_u32(As), bbase0 = smem_u32(Bs);

  float acc[2][8][4];
  #pragma unroll
  for (int mt=0;mt<2;mt++)
    #pragma unroll
    for (int nt=0;nt<8;nt++)
      #pragma unroll
      for (int e=0;e<4;e++) acc[mt][nt][e] = 0.f;

  #pragma unroll
  for (int i = 0; i < 4; i++){
    cp16(sAs + i*32*GST*4, Ag + (size_t)i*32*EMB);
    cp16(sBs + i*32*GST*4, Wg + (size_t)i*32*EMB);
  }
  CP_COMMIT();

  for (int kt = 0; kt < 64; kt++){
    const int buf = kt & 1;
    if (kt < 63){
      const int nb = (kt+1) & 1;
      #pragma unroll
      for (int i = 0; i < 4; i++){
        cp16(sAs + (nb*TILE_F + i*32*GST)*4, Ag + (kt+1)*32 + (size_t)i*32*EMB);
        cp16(sBs + (nb*TILE_F + i*32*GST)*4, Wg + (kt+1)*32 + (size_t)i*32*EMB);
      }
    }
    CP_COMMIT();
    CP_WAIT1();
    __syncthreads();

    const uint32_t abase = abase0 + buf*TILE_F*4;
    const uint32_t bbase = bbase0 + buf*TILE_F*4;
    #pragma unroll
    for (int ks = 0; ks < 4; ks++){
      uint32_t af[2][4], bf[4][4];
      ldsm4(af[0], abase + offA[0] + ks*32);
      ldsm4(af[1], abase + offA[1] + ks*32);
      #pragma unroll
      for (int j=0;j<4;j++) ldsm4(bf[j], bbase + offB[j] + ks*32);
      #pragma unroll
      for (int mt=0; mt<2; mt++)
        #pragma unroll
        for (int j=0; j<4; j++){
          mma8(acc[mt][2*j],   af[mt], &bf[j][0]);
          mma8(acc[mt][2*j+1], af[mt], &bf[j][2]);
        }
    }
    __syncthreads();
  }

  if (mode <= 1){
    float* C = (mode==0) ? g_q : g_k;
    float* ex = smg;
    #pragma unroll
    for (int mt=0; mt<2; mt++){
      #pragma unroll
      for (int nt=0; nt<8; nt++){
        int colL = wn + nt*8 + 2*t4;
        float b0 = bias[bn*128 + colL], b1 = bias[bn*128 + colL + 1];
        int r0 = wm + mt*16 + g;
        ex[r0*EXST + colL]     = acc[mt][nt][0] + b0;
        ex[r0*EXST + colL + 1] = acc[mt][nt][1] + b1;
        ex[(r0+8)*EXST + colL]     = acc[mt][nt][2] + b0;
        ex[(r0+8)*EXST + colL + 1] = acc[mt][nt][3] + b1;
      }
    }
    __syncthreads();
    #pragma unroll
    for (int mt=0; mt<2; mt++){
      #pragma unroll
      for (int hh=0; hh<2; hh++){
        int rowL = wm + mt*16 + g + hh*8;
        int m = bm*128 + rowL;
        int s = m & (SEQ-1);
        float* Crow = C + (size_t)m * EMB + bn*128;
        #pragma unroll
        for (int nt=0; nt<8; nt++){
          int j = ((wn >> 1) + nt*4 + t4) & 63;
          float c = g_cos[s*64 + j], sn = g_sin[s*64 + j];
          float v1 = ex[rowL*EXST + j];
          float v2 = ex[rowL*EXST + j + 64];
          Crow[j]      = f2tff(v1*c - v2*sn);
          Crow[j + 64] = f2tff(v1*sn + v2*c);
        }
      }
    }
  } else if (mode == 2){
    float* ex = smg;
    #pragma unroll
    for (int mt=0; mt<2; mt++){
      #pragma unroll
      for (int nt=0; nt<8; nt++){
        int colL = wn + nt*8 + 2*t4;
        float b0 = bias[bn*128 + colL], b1 = bias[bn*128 + colL + 1];
        int r0 = wm + mt*16 + g;
        ex[colL*EXST_V + r0]       = f2tff(acc[mt][nt][0] + b0);
        ex[(colL+1)*EXST_V + r0]   = f2tff(acc[mt][nt][1] + b1);
        ex[colL*EXST_V + r0+8]     = f2tff(acc[mt][nt][2] + b0);
        ex[(colL+1)*EXST_V + r0+8] = f2tff(acc[mt][nt][3] + b1);
      }
    }
    __syncthreads();
    const int d  = tid >> 1;
    const int sh = (tid & 1) << 6;
    const int bb = bm >> 4;
    const int s_base = (bm & 15) * 128;
    float* Vt = g_v + (((size_t)(bb*NH + bn))*HD + d)*SEQ + s_base + sh;
    const float* exr = ex + d*EXST_V + sh;
    #pragma unroll
    for (int i = 0; i < 16; i++)
      *(float4*)&Vt[i*4] = *(const float4*)&exr[i*4];
  } else {
    #pragma unroll
    for (int mt=0; mt<2; mt++){
      int row = bm*128 + wm + mt*16 + g;
      #pragma unroll
      for (int nt=0; nt<8; nt++){
        int col = bn*128 + wn + nt*8 + 2*t4;
        float b0 = biasq[col], b1 = biasq[col+1];
        float2 v0 = make_float2(acc[mt][nt][0]+b0, acc[mt][nt][1]+b1);
        float2 v1 = make_float2(acc[mt][nt][2]+b0, acc[mt][nt][3]+b1);
        *(float2*)&Outp[(size_t)row*EMB + col] = v0;
        *(float2*)&Outp[(size_t)(row+8)*EMB + col] = v1;
      }
    }
  }
}

// ---------------------------------------------------------------------------
// Flash attention, causal (champion R12 form) + diag fully-masked S-mma skip.
// 256 thr, 4x2 warps, ldmatrix Q/K/P/V^T, split K/V cp.async groups,
// qt-descending grid.
// ---------------------------------------------------------------------------
#define FLASH_SMEM_FLOATS (3*128*FST + 256 + 256 + 128)

__global__ __launch_bounds__(256,1) void flash_kernel(const unsigned char* __restrict__ amask){
  extern __shared__ float sm[];
  float* Qs   = sm;
  float* Ks   = sm + 128*FST;
  float* Vs   = sm + 2*128*FST;       // V^T tile: [d=0..127][s=0..127]
  float* redm = sm + 3*128*FST;
  float* reds = redm + 256;
  float* km   = reds + 256;

  const int tid = threadIdx.x;
  const int bh = blockIdx.x;
  const int qt = (int)(gridDim.y - 1) - (int)blockIdx.y;  // long CTAs first
  const int b = bh >> 4, h = bh & 15;
  const int lane = tid & 31, w = tid >> 5;
  const int wm = (w >> 1) << 5;
  const int wnn = (w & 1);
  const int wn = wnn << 6;
  const int g = lane >> 2, t4 = lane & 3;
  const int q8 = lane >> 3, r8 = lane & 7;

  const size_t headoff = (size_t)h * HD;
  const int lr = tid >> 5;
  const int lc = (tid & 31) << 2;

  const float* Qg = g_q + ((size_t)(b*SEQ + qt*128) + lr) * EMB + headoff + lc;
  const uint32_t qbase = smem_u32(Qs), kbase = smem_u32(Ks), vbase = smem_u32(Vs);
  const uint32_t sQ = qbase + (lr*FST + lc)*4;
  const uint32_t sK = kbase + (lr*FST + lc)*4;
  const uint32_t sV = vbase + (lr*FST + lc)*4;

  uint32_t offQA[2], offKB[4];
  #pragma unroll
  for (int mt=0; mt<2; mt++)
    offQA[mt] = (uint32_t)(((wm + mt*16 + ((q8&1)<<3) + r8)*FST + ((q8>>1)<<2))*4);
  #pragma unroll
  for (int j=0; j<4; j++)
    offKB[j] = (uint32_t)(((wn + j*16 + ((q8>>1)<<3) + r8)*FST + ((q8&1)<<2))*4);

  #pragma unroll
  for (int i = 0; i < 16; i++)
    cp16(sQ + i*8*FST*4, Qg + (size_t)i*8*EMB);
  CP_COMMIT();

  float o_acc[2][8][4];
  #pragma unroll
  for (int mt=0;mt<2;mt++)
    #pragma unroll
    for (int nt=0;nt<8;nt++)
      #pragma unroll
      for (int e=0;e<4;e++) o_acc[mt][nt][e] = 0.f;
  float m_prev[4], l_run[4];
  #pragma unroll
  for (int ri=0;ri<4;ri++){ m_prev[ri] = -1e30f; l_run[ri] = 0.f; }

  const float scale = 0.088388347648318447f;
  // this warp's S tile is fully causal-masked on the diagonal k-tile iff
  // its min col (wn) exceeds its max row (wm+31)
  const bool full_mask_diag = (wn > wm + 31);

  for (int kt = 0; kt <= qt; kt++){
    __syncthreads();   // prior PV reads of Ks/Vs done before refill
    const float* Kg = g_k + ((size_t)(b*SEQ + kt*128) + lr) * EMB + headoff + lc;
    const float* Vg = g_v + ((size_t)bh*HD + lr)*SEQ + kt*128 + lc;
    #pragma unroll
    for (int i = 0; i < 16; i++)
      cp16(sK + i*8*FST*4, Kg + (size_t)i*8*EMB);
    CP_COMMIT();       // group A: K
    #pragma unroll
    for (int i = 0; i < 16; i++)
      cp16(sV + i*8*FST*4, Vg + (size_t)i*8*SEQ);
    CP_COMMIT();       // group B: V
    if (tid < 128) km[tid] = amask[b*SEQ + kt*128 + tid] ? -1e30f : 0.f;
    CP_WAIT1();        // K (and Q on first iter) resident; V may be in flight
    __syncthreads();

    const bool diag = (kt == qt);
    const bool skipS = diag && full_mask_diag;   // warp-uniform

    // ---- S = Q K^T ----
    float s_acc[2][8][4];
    #pragma unroll
    for (int mt=0;mt<2;mt++)
      #pragma unroll
      for (int nt=0;nt<8;nt++)
        #pragma unroll
        for (int e=0;e<4;e++) s_acc[mt][nt][e] = 0.f;

    if (!skipS){
      #pragma unroll
      for (int ks=0; ks<16; ks++){
        uint32_t af[2][4], bf[4][4];
        ldsm4(af[0], qbase + offQA[0] + ks*32);
        ldsm4(af[1], qbase + offQA[1] + ks*32);
        #pragma unroll
        for (int j=0;j<4;j++) ldsm4(bf[j], kbase + offKB[j] + ks*32);
        #pragma unroll
        for (int mt=0;mt<2;mt++)
          #pragma unroll
          for (int j=0;j<4;j++){
            mma8(s_acc[mt][2*j],   af[mt], &bf[j][0]);
            mma8(s_acc[mt][2*j+1], af[mt], &bf[j][2]);
          }
      }
    }

    #pragma unroll
    for (int mt=0;mt<2;mt++)
      #pragma unroll
      for (int nt=0;nt<8;nt++)
        #pragma unroll
        for (int e=0;e<4;e++){
          int colL = wn + nt*8 + 2*t4 + (e & 1);
          int rowL = wm + mt*16 + g + ((e >> 1) << 3);
          float v = s_acc[mt][nt][e]*scale + km[colL];
          if (diag && colL > rowL) v = -1e30f;
          s_acc[mt][nt][e] = v;
        }

    #pragma unroll
    for (int ri=0;ri<4;ri++){
      int mt = ri>>1, hh = ri&1;
      float mx = -1e30f;
      #pragma unroll
      for (int nt=0;nt<8;nt++)
        mx = fmaxf(mx, fmaxf(s_acc[mt][nt][hh*2], s_acc[mt][nt][hh*2+1]));
      mx = fmaxf(mx, __shfl_xor_sync(0xffffffffu, mx, 1));
      mx = fmaxf(mx, __shfl_xor_sync(0xffffffffu, mx, 2));
      if (t4 == 0) redm[wnn*128 + wm + mt*16 + g + hh*8] = mx;
    }
    __syncthreads();

    float m_new[4], alpha[4], rsum[4];
    #pragma unroll
    for (int ri=0;ri<4;ri++){
      int rl = wm + (ri>>1)*16 + g + (ri&1)*8;
      float mtile = fmaxf(redm[rl], redm[128+rl]);
      m_new[ri] = fmaxf(m_prev[ri], mtile);
      alpha[ri] = __expf(m_prev[ri] - m_new[ri]);
      rsum[ri] = 0.f;
    }

    #pragma unroll
    for (int mt=0;mt<2;mt++)
      #pragma unroll
      for (int nt=0;nt<8;nt++)
        #pragma unroll
        for (int hh=0;hh<2;hh++){
          int ri = mt*2 + hh;
          float p0 = __expf(s_acc[mt][nt][hh*2]   - m_new[ri]);
          float p1 = __expf(s_acc[mt][nt][hh*2+1] - m_new[ri]);
          rsum[ri] += p0 + p1;
          int rowL = wm + mt*16 + g + hh*8;
          int colL = wn + nt*8 + 2*t4;
          float2 pv; pv.x = f2tff(p0); pv.y = f2tff(p1);
          *(float2*)&Ks[rowL*FST + colL] = pv;
          o_acc[mt][nt][hh*2]   *= alpha[ri];
          o_acc[mt][nt][hh*2+1] *= alpha[ri];
        }

    #pragma unroll
    for (int ri=0;ri<4;ri++){
      float s0 = rsum[ri];
      s0 += __shfl_xor_sync(0xffffffffu, s0, 1);
      s0 += __shfl_xor_sync(0xffffffffu, s0, 2);
      if (t4 == 0) reds[wnn*128 + wm + (ri>>1)*16 + g + (ri&1)*8] = s0;
    }
    CP_WAIT0();        // V resident (hidden behind S + softmax)
    __syncthreads();   // P + sums + V all visible
    #pragma unroll
    for (int ri=0;ri<4;ri++){
      int rl = wm + (ri>>1)*16 + g + (ri&1)*8;
      l_run[ri] = l_run[ri]*alpha[ri] + reds[rl] + reds[128+rl];
      m_prev[ri] = m_new[ri];
    }

    // ---- O += P @ V ----
    #pragma unroll
    for (int ks=0; ks<16; ks++){
      uint32_t af[2][4], bf[4][4];
      ldsm4(af[0], kbase + offQA[0] + ks*32);
      ldsm4(af[1], kbase + offQA[1] + ks*32);
      #pragma unroll
      for (int j=0;j<4;j++) ldsm4(bf[j], vbase + offKB[j] + ks*32);
      #pragma unroll
      for (int mt=0;mt<2;mt++)
        #pragma unroll
        for (int j=0;j<4;j++){
          mma8(o_acc[mt][2*j],   af[mt], &bf[j][0]);
          mma8(o_acc[mt][2*j+1], af[mt], &bf[j][2]);
        }
    }
  }

  float* Og = g_o + ((size_t)(b*SEQ + qt*128)) * EMB + headoff;
  #pragma unroll
  for (int mt=0;mt<2;mt++)
    #pragma unroll
    for (int hh=0;hh<2;hh++){
      int ri = mt*2 + hh;
      float inv = 1.0f / l_run[ri];
      int rowL = wm + mt*16 + g + hh*8;
      #pragma unroll
      for (int nt=0;nt<8;nt++){
        int colL = wn + nt*8 + 2*t4;
        float2 ov;
        ov.x = f2tff(o_acc[mt][nt][hh*2]   * inv);
        ov.y = f2tff(o_acc[mt][nt][hh*2+1] * inv);
        *(float2*)&Og[(size_t)rowL*EMB + colL] = ov;
      }
    }
}

// ---------------------------------------------------------------------------
extern "C" void kernel_launch(void* const* d_in, const int* in_sizes, int n_in,
                              void* d_out, int out_size){
  (void)in_sizes; (void)n_in; (void)out_size;
  const float* x  = (const float*)d_in[0];
  const float* wq = (const float*)d_in[1];
  const float* bq = (const float*)d_in[2];
  const float* wk = (const float*)d_in[3];
  const float* bk = (const float*)d_in[4];
  const float* wv = (const float*)d_in[5];
  const float* bv = (const float*)d_in[6];
  const float* wo = (const float*)d_in[7];
  const float* bo = (const float*)d_in[8];
  const unsigned char* amask = (const unsigned char*)d_in[10];
  float* out = (float*)d_out;

  cudaFuncSetAttribute(flash_kernel, cudaFuncAttributeMaxDynamicSharedMemorySize,
                       FLASH_SMEM_FLOATS * (int)sizeof(float));

  float *p_x, *p_wq, *p_wk, *p_wv, *p_wo;
  cudaGetSymbolAddress((void**)&p_x,  g_x);
  cudaGetSymbolAddress((void**)&p_wq, g_wq);
  cudaGetSymbolAddress((void**)&p_wk, g_wk);
  cudaGetSymbolAddress((void**)&p_wv, g_wv);
  cudaGetSymbolAddress((void**)&p_wo, g_wo);

  rope_tables_kernel<<<(SEQ*64 + 255)/256, 256>>>();

  const int nAll4 = (1<<21) + 4*(1<<20);
  round_all_kernel<<<(nAll4+255)/256, 256>>>(x, wq, wk, wv, wo,
                                             p_x, p_wq, p_wk, p_wv, p_wo);

  gemm_bias_kernel<<<dim3(EMB/128, MTOT/128, 3), 256>>>(bq, bk, bv, nullptr, -1);

  flash_kernel<<<dim3(NB*NH, SEQ/128), 256, FLASH_SMEM_FLOATS*(int)sizeof(float)>>>(amask);

  gemm_bias_kernel<<<dim3(EMB/128, MTOT/128, 1), 256>>>(bo, bo, bo, out, 3);
}